// round 10
// baseline (speedup 1.0000x reference)
#include <cuda_runtime.h>
#include <cuda_fp16.h>

#define BATCH    65536
#define D1       196
#define D2       206
#define NP       208
#define TM       128         // batch rows per CTA
#define NTHREADS 512
#define DT2      0.01f
#define NKT      13          // k16 tiles
#define NNT      26          // n8 octets
#define CHUNK_U4 (NNT * 32)  // 832 uint4 per k16 chunk
#define B_U4     (NKT * CHUNK_U4)    // 10816 uint4 = 173056 B per stage
#define AFRAG_U32 (8 * NKT * 4 * 32) // 13312 u32 = 53248 B

__device__ float g_M1[NP * NP];
__device__ float g_M2[NP * NP];
__device__ uint4 g_B1[B_U4];   // pre-fragmented fp16 hi/lo B (stage 1)
__device__ uint4 g_B2[B_U4];   // stage 2

typedef unsigned u32;

// ---------- helpers ----------
__device__ __forceinline__ u32 pack_h2(float lo, float hi) {
    __half2 v = __floats2half2_rn(lo, hi);   // .x = lo (even k)
    return *reinterpret_cast<u32*>(&v);
}
__device__ __forceinline__ void split2h(float v0, float v1, u32& hi, u32& lo) {
    __half h0 = __float2half_rn(v0);
    __half h1 = __float2half_rn(v1);
    __half2 hh = __halves2half2(h0, h1);
    hi = *reinterpret_cast<u32*>(&hh);
    __half2 ll = __floats2half2_rn(v0 - __half2float(h0), v1 - __half2float(h1));
    lo = *reinterpret_cast<u32*>(&ll);
}
__device__ __forceinline__ void mma16816h(float (&d)[4],
                                          u32 a0, u32 a1, u32 a2, u32 a3,
                                          u32 b0, u32 b1) {
    asm volatile(
        "mma.sync.aligned.m16n8k16.row.col.f32.f16.f16.f32 "
        "{%0,%1,%2,%3}, {%4,%5,%6,%7}, {%8,%9}, {%0,%1,%2,%3};"
        : "+f"(d[0]), "+f"(d[1]), "+f"(d[2]), "+f"(d[3])
        : "r"(a0), "r"(a1), "r"(a2), "r"(a3), "r"(b0), "r"(b1));
}
__device__ __forceinline__ u32 smem_u32(const void* p) {
    u32 a;
    asm("{ .reg .u64 t; cvta.to.shared.u64 t, %1; cvt.u32.u64 %0, t; }" : "=r"(a) : "l"(p));
    return a;
}
#define CP16(dst, src) asm volatile("cp.async.cg.shared.global [%0], [%1], 16;" :: "r"(dst), "l"(src) : "memory")
#define CP_WAIT() asm volatile("cp.async.commit_group;\ncp.async.wait_group 0;" ::: "memory")

// ---------- prep 1: M = c2q(C) + Qn - I, zero-padded to NP x NP ----------
__global__ void prep_kernel(const float* __restrict__ C,
                            const float* __restrict__ Qn, int n, int which)
{
    float* M = which ? g_M2 : g_M1;
    const int j = blockIdx.x;
    __shared__ float red[256];
    float s = 0.f;
    if (j < n)
        for (int i = threadIdx.x; i < n; i += 256)
            s += 0.5f * (C[i * n + j] + C[j * n + i]);
    red[threadIdx.x] = s;
    __syncthreads();
    for (int off = 128; off > 0; off >>= 1) {
        if ((int)threadIdx.x < off) red[threadIdx.x] += red[threadIdx.x + off];
        __syncthreads();
    }
    const float colsum = red[0];
    for (int i = threadIdx.x; i < NP; i += 256) {
        float v = 0.f;
        if (j < n && i < n) {
            if (i == j) v = -colsum + Qn[j * n + j] - 1.0f;
            else        v = 0.5f * (C[i * n + j] + C[j * n + i]) + Qn[i * n + j];
        }
        M[i * NP + j] = v;
    }
}

// ---------- prep 2: pack M into mma b-fragment layout (fp16 hi/lo splits) ----------
__global__ void prep_frag(int which)
{
    const float* M = which ? g_M2 : g_M1;
    uint4* outB    = which ? g_B2 : g_B1;
    const int idx = blockIdx.x * blockDim.x + threadIdx.x;
    if (idx >= NKT * NNT * 32) return;
    const int lane = idx & 31;
    const int nt   = (idx >> 5) % NNT;
    const int kt   = (idx >> 5) / NNT;
    const int n  = nt * 8 + (lane >> 2);
    const int k0 = kt * 16 + (lane & 3) * 2;
    u32 bh0, bl0, bh1, bl1;
    split2h(M[k0 * NP + n],       M[(k0 + 1) * NP + n], bh0, bl0);
    split2h(M[(k0 + 8) * NP + n], M[(k0 + 9) * NP + n], bh1, bl1);
    outB[(kt * NNT + nt) * 32 + lane] = make_uint4(bh0, bh1, bl0, bl1);
}

// ---------- main fused kernel ----------
__global__ void __launch_bounds__(NTHREADS, 1)
net_kernel(const float* __restrict__ x,
           const float* __restrict__ b1,
           const float* __restrict__ b2,
           const float* __restrict__ facp,
           float* __restrict__ out)
{
    extern __shared__ __align__(16) unsigned char smraw[];
    u32*   Afrag = (u32*)smraw;                                   // 53248 B
    uint4* Bs    = (uint4*)(smraw + AFRAG_U32 * 4);               // 173056 B
    float* es1   = (float*)(smraw + AFRAG_U32 * 4 + B_U4 * 16);   // 208 f
    float* es2   = es1 + NP;

    const int tid  = threadIdx.x;
    const int lane = tid & 31, warp = tid >> 5;
    const int h     = (warp >> 2) & 1;             // col half (104 cols)
    const int rtile = (warp & 3) | ((warp >> 3) << 2);  // 8 row-tiles of 16
    const int g  = lane >> 2, t = lane & 3;
    const int rowg = blockIdx.x * TM;
    const int r0 = rtile * 16 + g;                 // owned rows r0, r0+8
    const u32 bsa = smem_u32(Bs);

    // start async copy of stage-1 B (never touched before first CP_WAIT)
    for (int i = tid; i < B_U4; i += NTHREADS)
        CP16(bsa + i * 16, (const uint4*)g_B1 + i);

    // biases for both stages
    for (int i = tid; i < NP; i += NTHREADS) {
        es1[i] = (i < D1) ? b1[i] : 0.f;
        es2[i] = (i < D2) ? b2[i] : 0.f;
    }

    float q[13][4];
    float acc[13][4];

    // q0 = x (zero-padded); col pairs never straddle 196 (even boundary)
    #pragma unroll
    for (int nt = 0; nt < 13; nt++) {
        const int col = (h * 13 + nt) * 8 + 2 * t;
        if (col < D1) {
            const float2 v0 = *(const float2*)&x[(size_t)(rowg + r0) * D1 + col];
            const float2 v1 = *(const float2*)&x[(size_t)(rowg + r0 + 8) * D1 + col];
            q[nt][0] = v0.x; q[nt][1] = v0.y; q[nt][2] = v1.x; q[nt][3] = v1.y;
        } else {
            q[nt][0] = q[nt][1] = q[nt][2] = q[nt][3] = 0.f;
        }
    }
    __syncthreads();   // es1/es2 writes visible before first acc init

    // write A = 4*sin(1.1 q) as single-fp16 fragments
    auto write_A = [&] {
        #pragma unroll
        for (int nt = 0; nt < 13; nt++) {
            const int NT = h * 13 + nt;
            const int kt = NT >> 1;
            const int rb = (NT & 1) ? 2 : 0;
            u32* base = &Afrag[((rtile * 13 + kt) * 4) * 32 + lane];
            base[rb * 32] =
                pack_h2(4.f * __sinf(1.1f * q[nt][0]), 4.f * __sinf(1.1f * q[nt][1]));
            base[(rb + 1) * 32] =
                pack_h2(4.f * __sinf(1.1f * q[nt][2]), 4.f * __sinf(1.1f * q[nt][3]));
        }
    };

    // acc += A @ M  (fp16 2-term: a*bh + a*bl); B fully resident, no syncs
    auto gemm_full = [&] {
        #pragma unroll 1
        for (int kt = 0; kt < NKT; kt++) {
            const u32* Ab = &Afrag[((rtile * 13 + kt) * 4) * 32 + lane];
            const u32 a0 = Ab[0], a1 = Ab[32], a2 = Ab[64], a3 = Ab[96];
            const uint4* Bw = Bs + kt * CHUNK_U4 + (h * 13) * 32 + lane;
            #pragma unroll
            for (int nt = 0; nt < 13; nt++) {
                const uint4 b = Bw[nt * 32];
                mma16816h(acc[nt], a0, a1, a2, a3, b.x, b.y);  // a*bh
                mma16816h(acc[nt], a0, a1, a2, a3, b.z, b.w);  // a*bl
            }
        }
    };
    // skinny: only n-tiles 24,25 (cols 192..207) -> h==1 warps, nt 11..12
    auto gemm_skinny = [&] {
        if (h == 1) {
            #pragma unroll 1
            for (int kt = 0; kt < NKT; kt++) {
                const u32* Ab = &Afrag[((rtile * 13 + kt) * 4) * 32 + lane];
                const u32 a0 = Ab[0], a1 = Ab[32], a2 = Ab[64], a3 = Ab[96];
                const uint4* Bw = Bs + kt * CHUNK_U4 + 13 * 32 + lane;
                #pragma unroll
                for (int nt = 11; nt < 13; nt++) {
                    const uint4 b = Bw[nt * 32];
                    mma16816h(acc[nt], a0, a1, a2, a3, b.x, b.y);
                    mma16816h(acc[nt], a0, a1, a2, a3, b.z, b.w);
                }
            }
        }
    };

    const float fac = *facp;

    #pragma unroll 1
    for (int st = 0; st < 2; st++) {
        const float* es = st ? es2 : es1;

        // ---- gemm 1: acc = 4e; A = 4*s(q0)  =>  acc = 4*(e + s0@M) = 4*a0 ----
        #pragma unroll
        for (int nt = 0; nt < 13; nt++) {
            const float2 e2 = *(const float2*)&es[(h * 13 + nt) * 8 + 2 * t];
            acc[nt][0] = 4.f * e2.x; acc[nt][1] = 4.f * e2.y;
            acc[nt][2] = 4.f * e2.x; acc[nt][3] = 4.f * e2.y;
        }
        write_A();
        if (st == 0) CP_WAIT();            // stage-1 B resident
        __syncthreads();                   // A + B visible
        gemm_full();
        __syncthreads();                   // all A reads done before overwrite

        // ---- readback: q2,q3; A = u = 2*s(q2)+s(q3);
        //      acc_old = 4e + 4*s0@M; fold: acc = q3/dt^2 + 3e + acc_old
        //        (= q3/dt^2 + 7e + 4*s0@M, so q5 = dt^2*(acc + u@M)) ----
        #pragma unroll
        for (int nt = 0; nt < 13; nt++) {
            const int NT = h * 13 + nt;
            const int kt = NT >> 1;
            const int rb = (NT & 1) ? 2 : 0;
            u32* base = &Afrag[((rtile * 13 + kt) * 4) * 32 + lane];
            float u[4];
            #pragma unroll
            for (int j = 0; j < 4; j++) {
                const int col = NT * 8 + 2 * t + (j & 1);
                const float a0v = 0.25f * acc[nt][j];
                const float q2 = q[nt][j] + DT2 * a0v;
                const float q3 = q[nt][j] + 3.0f * DT2 * a0v;
                u[j] = 2.0f * __sinf(1.1f * q2) + __sinf(1.1f * q3);
                acc[nt][j] = q3 * (1.0f / DT2) + 3.0f * es[col] + acc[nt][j];
            }
            base[rb * 32]       = pack_h2(u[0], u[1]);
            base[(rb + 1) * 32] = pack_h2(u[2], u[3]);
        }
        __syncthreads();

        // ---- gemm 2: acc += u @ M ;  q5 = dt^2 * acc ----
        if (st == 0) gemm_full();
        else         gemm_skinny();
        __syncthreads();                   // all B reads done before B swap

        if (st == 0) {
            // prefetch stage-2 B; overlapped with epilogue + next write_A
            for (int i = tid; i < B_U4; i += NTHREADS)
                CP16(bsa + i * 16, (const uint4*)g_B2 + i);
            #pragma unroll
            for (int nt = 0; nt < 13; nt++)
                #pragma unroll
                for (int j = 0; j < 4; j++)
                    q[nt][j] = DT2 * acc[nt][j];
            CP_WAIT();                     // stage-2 B resident (bar in next iter)
        } else {
            // output: q5 only for cols 196..205 (h==1, nt 11,12)
            if (h == 1) {
                #pragma unroll
                for (int nt = 11; nt < 13; nt++) {
                    const int NT = 13 + nt;
                    #pragma unroll
                    for (int j = 0; j < 4; j++) {
                        const int col = NT * 8 + 2 * t + (j & 1);
                        if (col >= D1 && col < D2) {
                            const float q5 = DT2 * acc[nt][j];
                            const int row = rowg + r0 + ((j >> 1) << 3);
                            out[(size_t)row * 10 + (col - D1)] = fac * q5;
                        }
                    }
                }
            }
        }
    }
}

extern "C" void kernel_launch(void* const* d_in, const int* in_sizes, int n_in,
                              void* d_out, int out_size)
{
    const float* x    = (const float*)d_in[0];
    const float* fc1w = (const float*)d_in[1];
    const float* fc1b = (const float*)d_in[2];
    const float* fc2w = (const float*)d_in[3];
    const float* fc2b = (const float*)d_in[4];
    const float* fac  = (const float*)d_in[5];
    const float* qn1  = (const float*)d_in[6];
    const float* qn2  = (const float*)d_in[7];
    float* out = (float*)d_out;

    prep_kernel<<<NP, 256>>>(fc1w, qn1, D1, 0);
    prep_kernel<<<NP, 256>>>(fc2w, qn2, D2, 1);
    const int nfrag = NKT * NNT * 32;
    prep_frag<<<(nfrag + 255) / 256, 256>>>(0);
    prep_frag<<<(nfrag + 255) / 256, 256>>>(1);

    const int smem = AFRAG_U32 * 4 + B_U4 * 16 + 2 * NP * 4;   // 227968 B
    cudaFuncSetAttribute(net_kernel,
                         cudaFuncAttributeMaxDynamicSharedMemorySize, smem);
    net_kernel<<<BATCH / TM, NTHREADS, smem>>>(x, fc1b, fc2b, fac, out);
}

// round 11
// speedup vs baseline: 1.5675x; 1.5675x over previous
#include <cuda_runtime.h>
#include <cuda_fp16.h>

#define BATCH    65536
#define D1       196
#define D2       206
#define NP       208
#define TM       64          // batch rows per CTA
#define NTHREADS 256
#define DT2      0.01f
#define NKT      13          // k16 tiles
#define NNT      26          // n8 octets
#define CHUNK_U2 (NNT * 32)            // 832 uint2 per k16 chunk
#define B_U2     (NKT * CHUNK_U2)      // 10816 uint2 = 86528 B per stage
#define B_CP16   (B_U2 / 2)            // 5408 16-byte packets
#define AFRAG_U32 (4 * NKT * 4 * 32)   // 6656 u32 = 26624 B

__device__ float g_M1[NP * NP];
__device__ float g_M2[NP * NP];
__device__ __align__(16) uint2 g_B1[B_U2];   // fp16 B fragments (stage 1)
__device__ __align__(16) uint2 g_B2[B_U2];   // stage 2

typedef unsigned u32;

// ---------- helpers ----------
__device__ __forceinline__ u32 pack_h2(float lo, float hi) {
    __half2 v = __floats2half2_rn(lo, hi);   // .x = lo (even k)
    return *reinterpret_cast<u32*>(&v);
}
__device__ __forceinline__ void mma16816h(float (&d)[4],
                                          u32 a0, u32 a1, u32 a2, u32 a3,
                                          u32 b0, u32 b1) {
    asm volatile(
        "mma.sync.aligned.m16n8k16.row.col.f32.f16.f16.f32 "
        "{%0,%1,%2,%3}, {%4,%5,%6,%7}, {%8,%9}, {%0,%1,%2,%3};"
        : "+f"(d[0]), "+f"(d[1]), "+f"(d[2]), "+f"(d[3])
        : "r"(a0), "r"(a1), "r"(a2), "r"(a3), "r"(b0), "r"(b1));
}
__device__ __forceinline__ u32 smem_u32(const void* p) {
    u32 a;
    asm("{ .reg .u64 t; cvta.to.shared.u64 t, %1; cvt.u32.u64 %0, t; }" : "=r"(a) : "l"(p));
    return a;
}
#define CP16(dst, src) asm volatile("cp.async.cg.shared.global [%0], [%1], 16;" :: "r"(dst), "l"(src) : "memory")
#define CP_WAIT() asm volatile("cp.async.commit_group;\ncp.async.wait_group 0;" ::: "memory")

// ---------- prep 1: M = c2q(C) + Qn - I, zero-padded to NP x NP ----------
__global__ void prep_kernel(const float* __restrict__ C,
                            const float* __restrict__ Qn, int n, int which)
{
    float* M = which ? g_M2 : g_M1;
    const int j = blockIdx.x;
    __shared__ float red[256];
    float s = 0.f;
    if (j < n)
        for (int i = threadIdx.x; i < n; i += 256)
            s += 0.5f * (C[i * n + j] + C[j * n + i]);
    red[threadIdx.x] = s;
    __syncthreads();
    for (int off = 128; off > 0; off >>= 1) {
        if ((int)threadIdx.x < off) red[threadIdx.x] += red[threadIdx.x + off];
        __syncthreads();
    }
    const float colsum = red[0];
    for (int i = threadIdx.x; i < NP; i += 256) {
        float v = 0.f;
        if (j < n && i < n) {
            if (i == j) v = -colsum + Qn[j * n + j] - 1.0f;
            else        v = 0.5f * (C[i * n + j] + C[j * n + i]) + Qn[i * n + j];
        }
        M[i * NP + j] = v;
    }
}

// ---------- prep 2: pack M into mma b-fragment layout (single fp16) ----------
// b0 of tile (kt,nt): B[k=16kt+2t+{0,1}][n=8nt+g]; b1: k offset +8. (g=lane>>2,t=lane&3)
__global__ void prep_frag(int which)
{
    const float* M = which ? g_M2 : g_M1;
    uint2* outB    = which ? g_B2 : g_B1;
    const int idx = blockIdx.x * blockDim.x + threadIdx.x;
    if (idx >= NKT * NNT * 32) return;
    const int lane = idx & 31;
    const int nt   = (idx >> 5) % NNT;
    const int kt   = (idx >> 5) / NNT;
    const int n  = nt * 8 + (lane >> 2);
    const int k0 = kt * 16 + (lane & 3) * 2;
    uint2 b;
    b.x = pack_h2(M[k0 * NP + n],       M[(k0 + 1) * NP + n]);
    b.y = pack_h2(M[(k0 + 8) * NP + n], M[(k0 + 9) * NP + n]);
    outB[(kt * NNT + nt) * 32 + lane] = b;
}

// ---------- main fused kernel ----------
__global__ void __launch_bounds__(NTHREADS, 2)
net_kernel(const float* __restrict__ x,
           const float* __restrict__ b1,
           const float* __restrict__ b2,
           const float* __restrict__ facp,
           float* __restrict__ out)
{
    extern __shared__ __align__(16) unsigned char smraw[];
    u32*   Afrag = (u32*)smraw;                                   // 26624 B
    uint2* Bs    = (uint2*)(smraw + AFRAG_U32 * 4);               // 86528 B
    float* es1   = (float*)(smraw + AFRAG_U32 * 4 + B_U2 * 8);    // 208 f
    float* es2   = es1 + NP;

    const int tid  = threadIdx.x;
    const int lane = tid & 31, warp = tid >> 5;
    const int rtile = warp & 3;     // 4 row-tiles of 16
    const int h     = warp >> 2;    // col half (104 cols)
    const int g  = lane >> 2, t = lane & 3;
    const int rowg = blockIdx.x * TM;
    const int r0 = rtile * 16 + g;  // owned rows r0, r0+8
    const u32 bsa = smem_u32(Bs);

    // start async copy of stage-1 B (never touched before first CP_WAIT)
    for (int i = tid; i < B_CP16; i += NTHREADS)
        CP16(bsa + i * 16, (const char*)g_B1 + i * 16);

    // biases for both stages
    for (int i = tid; i < NP; i += NTHREADS) {
        es1[i] = (i < D1) ? b1[i] : 0.f;
        es2[i] = (i < D2) ? b2[i] : 0.f;
    }

    float q[13][4];
    float acc[13][4];

    // q0 = x (zero-padded); col pairs never straddle 196 (even boundary)
    #pragma unroll
    for (int nt = 0; nt < 13; nt++) {
        const int col = (h * 13 + nt) * 8 + 2 * t;
        if (col < D1) {
            const float2 v0 = *(const float2*)&x[(size_t)(rowg + r0) * D1 + col];
            const float2 v1 = *(const float2*)&x[(size_t)(rowg + r0 + 8) * D1 + col];
            q[nt][0] = v0.x; q[nt][1] = v0.y; q[nt][2] = v1.x; q[nt][3] = v1.y;
        } else {
            q[nt][0] = q[nt][1] = q[nt][2] = q[nt][3] = 0.f;
        }
    }
    __syncthreads();   // es1/es2 writes visible before first acc init

    // write A = 4*sin(1.1 q) as single-fp16 fragments
    auto write_A = [&] {
        #pragma unroll
        for (int nt = 0; nt < 13; nt++) {
            const int NT = h * 13 + nt;
            const int kt = NT >> 1;
            const int rb = (NT & 1) ? 2 : 0;
            u32* base = &Afrag[((rtile * 13 + kt) * 4) * 32 + lane];
            base[rb * 32] =
                pack_h2(4.f * __sinf(1.1f * q[nt][0]), 4.f * __sinf(1.1f * q[nt][1]));
            base[(rb + 1) * 32] =
                pack_h2(4.f * __sinf(1.1f * q[nt][2]), 4.f * __sinf(1.1f * q[nt][3]));
        }
    };

    // acc += A @ M (single-term fp16); B fully resident, no inner syncs
    auto gemm_full = [&] {
        #pragma unroll 1
        for (int kt = 0; kt < NKT; kt++) {
            const u32* Ab = &Afrag[((rtile * 13 + kt) * 4) * 32 + lane];
            const u32 a0 = Ab[0], a1 = Ab[32], a2 = Ab[64], a3 = Ab[96];
            const uint2* Bw = Bs + kt * CHUNK_U2 + (h * 13) * 32 + lane;
            #pragma unroll
            for (int nt = 0; nt < 13; nt++) {
                const uint2 b = Bw[nt * 32];
                mma16816h(acc[nt], a0, a1, a2, a3, b.x, b.y);
            }
        }
    };
    // skinny: only n-tiles 24,25 (cols 192..207) -> h==1 warps, nt 11..12
    auto gemm_skinny = [&] {
        if (h == 1) {
            #pragma unroll 1
            for (int kt = 0; kt < NKT; kt++) {
                const u32* Ab = &Afrag[((rtile * 13 + kt) * 4) * 32 + lane];
                const u32 a0 = Ab[0], a1 = Ab[32], a2 = Ab[64], a3 = Ab[96];
                const uint2* Bw = Bs + kt * CHUNK_U2 + 13 * 32 + lane;
                #pragma unroll
                for (int nt = 11; nt < 13; nt++) {
                    const uint2 b = Bw[nt * 32];
                    mma16816h(acc[nt], a0, a1, a2, a3, b.x, b.y);
                }
            }
        }
    };

    const float fac = *facp;

    #pragma unroll 1
    for (int st = 0; st < 2; st++) {
        const float* es = st ? es2 : es1;

        // ---- gemm 1: acc = 4e; A = 4*s(q0)  =>  acc = 4*(e + s0@M) = 4*a0 ----
        #pragma unroll
        for (int nt = 0; nt < 13; nt++) {
            const float2 e2 = *(const float2*)&es[(h * 13 + nt) * 8 + 2 * t];
            acc[nt][0] = 4.f * e2.x; acc[nt][1] = 4.f * e2.y;
            acc[nt][2] = 4.f * e2.x; acc[nt][3] = 4.f * e2.y;
        }
        write_A();
        if (st == 0) CP_WAIT();            // stage-1 B resident
        __syncthreads();                   // A + B visible
        gemm_full();
        __syncthreads();                   // all A reads done before overwrite

        // ---- readback: q2,q3; A = u = 2*s(q2)+s(q3);
        //      acc_old = 4e + 4*s0@M; fold: acc = q3/dt^2 + 3e + acc_old
        //        (= q3/dt^2 + 7e + 4*s0@M, so q5 = dt^2*(acc + u@M)) ----
        #pragma unroll
        for (int nt = 0; nt < 13; nt++) {
            const int NT = h * 13 + nt;
            const int kt = NT >> 1;
            const int rb = (NT & 1) ? 2 : 0;
            u32* base = &Afrag[((rtile * 13 + kt) * 4) * 32 + lane];
            float u[4];
            #pragma unroll
            for (int j = 0; j < 4; j++) {
                const int col = NT * 8 + 2 * t + (j & 1);
                const float a0v = 0.25f * acc[nt][j];
                const float q2 = q[nt][j] + DT2 * a0v;
                const float q3 = q[nt][j] + 3.0f * DT2 * a0v;
                u[j] = 2.0f * __sinf(1.1f * q2) + __sinf(1.1f * q3);
                acc[nt][j] = q3 * (1.0f / DT2) + 3.0f * es[col] + acc[nt][j];
            }
            base[rb * 32]       = pack_h2(u[0], u[1]);
            base[(rb + 1) * 32] = pack_h2(u[2], u[3]);
        }
        __syncthreads();

        // ---- gemm 2: acc += u @ M ;  q5 = dt^2 * acc ----
        if (st == 0) gemm_full();
        else         gemm_skinny();
        __syncthreads();                   // all B reads done before B swap

        if (st == 0) {
            // prefetch stage-2 B; overlapped with epilogue + next write_A
            for (int i = tid; i < B_CP16; i += NTHREADS)
                CP16(bsa + i * 16, (const char*)g_B2 + i * 16);
            #pragma unroll
            for (int nt = 0; nt < 13; nt++)
                #pragma unroll
                for (int j = 0; j < 4; j++)
                    q[nt][j] = DT2 * acc[nt][j];
            CP_WAIT();                     // stage-2 B resident (bar in next iter)
        } else {
            // output: q5 only for cols 196..205 (h==1, nt 11,12)
            if (h == 1) {
                #pragma unroll
                for (int nt = 11; nt < 13; nt++) {
                    const int NT = 13 + nt;
                    #pragma unroll
                    for (int j = 0; j < 4; j++) {
                        const int col = NT * 8 + 2 * t + (j & 1);
                        if (col >= D1 && col < D2) {
                            const float q5 = DT2 * acc[nt][j];
                            const int row = rowg + r0 + ((j >> 1) << 3);
                            out[(size_t)row * 10 + (col - D1)] = fac * q5;
                        }
                    }
                }
            }
        }
    }
}

extern "C" void kernel_launch(void* const* d_in, const int* in_sizes, int n_in,
                              void* d_out, int out_size)
{
    const float* x    = (const float*)d_in[0];
    const float* fc1w = (const float*)d_in[1];
    const float* fc1b = (const float*)d_in[2];
    const float* fc2w = (const float*)d_in[3];
    const float* fc2b = (const float*)d_in[4];
    const float* fac  = (const float*)d_in[5];
    const float* qn1  = (const float*)d_in[6];
    const float* qn2  = (const float*)d_in[7];
    float* out = (float*)d_out;

    prep_kernel<<<NP, 256>>>(fc1w, qn1, D1, 0);
    prep_kernel<<<NP, 256>>>(fc2w, qn2, D2, 1);
    const int nfrag = NKT * NNT * 32;
    prep_frag<<<(nfrag + 255) / 256, 256>>>(0);
    prep_frag<<<(nfrag + 255) / 256, 256>>>(1);

    const int smem = AFRAG_U32 * 4 + B_U2 * 8 + 2 * NP * 4;   // 114816 B
    cudaFuncSetAttribute(net_kernel,
                         cudaFuncAttributeMaxDynamicSharedMemorySize, smem);
    net_kernel<<<BATCH / TM, NTHREADS, smem>>>(x, fc1b, fc2b, fac, out);
}

// round 12
// speedup vs baseline: 1.7130x; 1.0929x over previous
#include <cuda_runtime.h>
#include <cuda_fp16.h>

#define BATCH    65536
#define D1       196
#define D2       206
#define NP       208
#define TM       64          // batch rows per CTA
#define NTHREADS 256
#define DT2      0.01f
#define NKT      13          // k16 tiles
#define NNT      26          // n8 octets
#define B_U32    (NKT * 2 * 832)       // 21632 u32 = 86528 B per stage
#define B_CP16   (B_U32 / 4)           // 5408 16-byte packets
#define AFRAG_U32 (4 * NKT * 4 * 32)   // 6656 u32 = 26624 B

typedef unsigned u32;

__device__ float g_diag[2][NP];                     // c2q diagonal + Qn - 1
__device__ __align__(16) u32 g_B1[B_U32];           // paired fp16 B frags (stage 1)
__device__ __align__(16) u32 g_B2[B_U32];           // stage 2

// ---------- helpers ----------
__device__ __forceinline__ u32 pack_h2(float lo, float hi) {
    __half2 v = __floats2half2_rn(lo, hi);   // .x = lo (even k)
    return *reinterpret_cast<u32*>(&v);
}
__device__ __forceinline__ void mma16816h(float (&d)[4],
                                          u32 a0, u32 a1, u32 a2, u32 a3,
                                          u32 b0, u32 b1) {
    asm volatile(
        "mma.sync.aligned.m16n8k16.row.col.f32.f16.f16.f32 "
        "{%0,%1,%2,%3}, {%4,%5,%6,%7}, {%8,%9}, {%0,%1,%2,%3};"
        : "+f"(d[0]), "+f"(d[1]), "+f"(d[2]), "+f"(d[3])
        : "r"(a0), "r"(a1), "r"(a2), "r"(a3), "r"(b0), "r"(b1));
}
__device__ __forceinline__ u32 smem_u32(const void* p) {
    u32 a;
    asm("{ .reg .u64 t; cvta.to.shared.u64 t, %1; cvt.u32.u64 %0, t; }" : "=r"(a) : "l"(p));
    return a;
}
#define CP16(dst, src) asm volatile("cp.async.cg.shared.global [%0], [%1], 16;" :: "r"(dst), "l"(src) : "memory")
#define CP_WAIT() asm volatile("cp.async.commit_group;\ncp.async.wait_group 0;" ::: "memory")

// ---------- prep A: column sums -> diagonal values, both stages ----------
__global__ void prep_colsum(const float* __restrict__ C1, const float* __restrict__ Qn1,
                            const float* __restrict__ C2, const float* __restrict__ Qn2)
{
    const int st = blockIdx.x / NP;
    const int j  = blockIdx.x % NP;
    const int n  = st ? D2 : D1;
    const float* C  = st ? C2 : C1;
    const float* Qn = st ? Qn2 : Qn1;
    __shared__ float red[128];
    float s = 0.f;
    if (j < n)
        for (int i = threadIdx.x; i < n; i += 128)
            s += 0.5f * (C[i * n + j] + C[j * n + i]);
    red[threadIdx.x] = s;
    __syncthreads();
    for (int off = 64; off > 0; off >>= 1) {
        if ((int)threadIdx.x < off) red[threadIdx.x] += red[threadIdx.x + off];
        __syncthreads();
    }
    if (threadIdx.x == 0)
        g_diag[st][j] = (j < n) ? (-red[0] + Qn[j * n + j] - 1.0f) : 0.f;
}

// ---------- prep B: build paired fp16 mma B-fragments directly from C/Qn ----
// M[k][n] = 0.5*(C[k,n]+C[n,k]) + Qn[k,n]  (k!=n), diag from g_diag; 0 pad.
// Paired layout per (kt,h): 6 uint4 pair-groups (tiles 2p,2p+1) + 1 uint2 single.
__global__ void prep_frag(const float* __restrict__ C1, const float* __restrict__ Qn1,
                          const float* __restrict__ C2, const float* __restrict__ Qn2)
{
    const int idx = blockIdx.x * blockDim.x + threadIdx.x;
    if (idx >= 2 * NKT * NNT * 32) return;
    const int lane = idx & 31;
    const int NT   = (idx >> 5) % NNT;
    const int kt   = ((idx >> 5) / NNT) % NKT;
    const int st   = (idx >> 5) / (NNT * NKT);
    const int nd   = st ? D2 : D1;
    const float* C  = st ? C2 : C1;
    const float* Qn = st ? Qn2 : Qn1;
    const int nn = NT * 8 + (lane >> 2);
    const int k0 = kt * 16 + (lane & 3) * 2;
    auto elem = [&](int k) -> float {
        if (k >= nd || nn >= nd) return 0.f;
        if (k == nn) return g_diag[st][k];
        return 0.5f * (C[k * nd + nn] + C[nn * nd + k]) + Qn[k * nd + nn];
    };
    const u32 bx = pack_h2(elem(k0),     elem(k0 + 1));
    const u32 by = pack_h2(elem(k0 + 8), elem(k0 + 9));
    u32* B = st ? g_B2 : g_B1;
    const int h = NT / 13, ntl = NT % 13;
    const int gbase = (kt * 2 + h) * 832;
    if (ntl < 12) {
        const int pair = ntl >> 1, sub = ntl & 1;
        B[gbase + pair * 128 + lane * 4 + sub * 2]     = bx;
        B[gbase + pair * 128 + lane * 4 + sub * 2 + 1] = by;
    } else {
        B[gbase + 768 + lane * 2]     = bx;
        B[gbase + 768 + lane * 2 + 1] = by;
    }
}

// ---------- main fused kernel ----------
__global__ void __launch_bounds__(NTHREADS, 2)
net_kernel(const float* __restrict__ x,
           const float* __restrict__ b1,
           const float* __restrict__ b2,
           const float* __restrict__ facp,
           float* __restrict__ out)
{
    extern __shared__ __align__(16) unsigned char smraw[];
    u32*  Afrag = (u32*)smraw;                                  // 26624 B
    u32*  BsU   = (u32*)(smraw + AFRAG_U32 * 4);                // 86528 B
    float* es1  = (float*)(smraw + AFRAG_U32 * 4 + B_U32 * 4);  // 208 f
    float* es2  = es1 + NP;

    const int tid  = threadIdx.x;
    const int lane = tid & 31, warp = tid >> 5;
    const int rtile = warp & 3;     // 4 row-tiles of 16
    const int h     = warp >> 2;    // col half (104 cols)
    const int g  = lane >> 2, t = lane & 3;
    const int rowg = blockIdx.x * TM;
    const int r0 = rtile * 16 + g;  // owned rows r0, r0+8
    const u32 bsa = smem_u32(BsU);

    // start async copy of stage-1 B (never touched before first CP_WAIT)
    for (int i = tid; i < B_CP16; i += NTHREADS)
        CP16(bsa + i * 16, (const char*)g_B1 + i * 16);

    // biases for both stages
    for (int i = tid; i < NP; i += NTHREADS) {
        es1[i] = (i < D1) ? b1[i] : 0.f;
        es2[i] = (i < D2) ? b2[i] : 0.f;
    }

    float q[13][4];
    float acc[13][4];

    // q0 = x (zero-padded); col pairs never straddle 196 (even boundary)
    #pragma unroll
    for (int nt = 0; nt < 13; nt++) {
        const int col = (h * 13 + nt) * 8 + 2 * t;
        if (col < D1) {
            const float2 v0 = *(const float2*)&x[(size_t)(rowg + r0) * D1 + col];
            const float2 v1 = *(const float2*)&x[(size_t)(rowg + r0 + 8) * D1 + col];
            q[nt][0] = v0.x; q[nt][1] = v0.y; q[nt][2] = v1.x; q[nt][3] = v1.y;
        } else {
            q[nt][0] = q[nt][1] = q[nt][2] = q[nt][3] = 0.f;
        }
    }
    __syncthreads();   // es1/es2 writes visible before first acc init

    // write A = 4*sin(1.1 q) as single-fp16 fragments
    auto write_A = [&] {
        #pragma unroll
        for (int nt = 0; nt < 13; nt++) {
            const int NT = h * 13 + nt;
            const int kt = NT >> 1;
            const int rb = (NT & 1) ? 2 : 0;
            u32* base = &Afrag[((rtile * 13 + kt) * 4) * 32 + lane];
            base[rb * 32] =
                pack_h2(4.f * __sinf(1.1f * q[nt][0]), 4.f * __sinf(1.1f * q[nt][1]));
            base[(rb + 1) * 32] =
                pack_h2(4.f * __sinf(1.1f * q[nt][2]), 4.f * __sinf(1.1f * q[nt][3]));
        }
    };

    // acc += A @ M (single-term fp16, paired-B LDS.128); no inner syncs
    auto gemm_full = [&] {
        #pragma unroll 1
        for (int kt = 0; kt < NKT; kt++) {
            const u32* Ab = &Afrag[((rtile * 13 + kt) * 4) * 32 + lane];
            const u32 a0 = Ab[0], a1 = Ab[32], a2 = Ab[64], a3 = Ab[96];
            const u32* Bg = BsU + (kt * 2 + h) * 832;
            #pragma unroll
            for (int p = 0; p < 6; p++) {
                const uint4 b = *(const uint4*)(Bg + p * 128 + lane * 4);
                mma16816h(acc[2 * p],     a0, a1, a2, a3, b.x, b.y);
                mma16816h(acc[2 * p + 1], a0, a1, a2, a3, b.z, b.w);
            }
            const uint2 bs2 = *(const uint2*)(Bg + 768 + lane * 2);
            mma16816h(acc[12], a0, a1, a2, a3, bs2.x, bs2.y);
        }
    };
    // skinny: only n-tiles 24,25 (cols 192..207) -> h==1 warps, nt 11..12
    auto gemm_skinny = [&] {
        if (h == 1) {
            #pragma unroll 1
            for (int kt = 0; kt < NKT; kt++) {
                const u32* Ab = &Afrag[((rtile * 13 + kt) * 4) * 32 + lane];
                const u32 a0 = Ab[0], a1 = Ab[32], a2 = Ab[64], a3 = Ab[96];
                const u32* Bg = BsU + (kt * 2 + 1) * 832;
                const uint4 b = *(const uint4*)(Bg + 5 * 128 + lane * 4);
                mma16816h(acc[11], a0, a1, a2, a3, b.z, b.w);
                const uint2 bs2 = *(const uint2*)(Bg + 768 + lane * 2);
                mma16816h(acc[12], a0, a1, a2, a3, bs2.x, bs2.y);
            }
        }
    };

    const float fac = *facp;

    #pragma unroll 1
    for (int st = 0; st < 2; st++) {
        const float* es = st ? es2 : es1;

        // ---- gemm 1: acc = 4e; A = 4*s(q0)  =>  acc = 4*(e + s0@M) = 4*a0 ----
        #pragma unroll
        for (int nt = 0; nt < 13; nt++) {
            const float2 e2 = *(const float2*)&es[(h * 13 + nt) * 8 + 2 * t];
            acc[nt][0] = 4.f * e2.x; acc[nt][1] = 4.f * e2.y;
            acc[nt][2] = 4.f * e2.x; acc[nt][3] = 4.f * e2.y;
        }
        write_A();
        if (st == 0) CP_WAIT();            // stage-1 B resident
        __syncthreads();                   // A + B visible
        gemm_full();
        __syncthreads();                   // all A reads done before overwrite

        // ---- readback: q2,q3; A = u = 2*s(q2)+s(q3);
        //      acc_old = 4e + 4*s0@M; fold: acc = q3/dt^2 + 3e + acc_old
        //        (= q3/dt^2 + 7e + 4*s0@M, so q5 = dt^2*(acc + u@M)) ----
        #pragma unroll
        for (int nt = 0; nt < 13; nt++) {
            const int NT = h * 13 + nt;
            const int kt = NT >> 1;
            const int rb = (NT & 1) ? 2 : 0;
            u32* base = &Afrag[((rtile * 13 + kt) * 4) * 32 + lane];
            float u[4];
            #pragma unroll
            for (int j = 0; j < 4; j++) {
                const int col = NT * 8 + 2 * t + (j & 1);
                const float a0v = 0.25f * acc[nt][j];
                const float q2 = q[nt][j] + DT2 * a0v;
                const float q3 = q[nt][j] + 3.0f * DT2 * a0v;
                u[j] = 2.0f * __sinf(1.1f * q2) + __sinf(1.1f * q3);
                acc[nt][j] = q3 * (1.0f / DT2) + 3.0f * es[col] + acc[nt][j];
            }
            base[rb * 32]       = pack_h2(u[0], u[1]);
            base[(rb + 1) * 32] = pack_h2(u[2], u[3]);
        }
        __syncthreads();

        // ---- gemm 2: acc += u @ M ;  q5 = dt^2 * acc ----
        if (st == 0) gemm_full();
        else         gemm_skinny();
        __syncthreads();                   // all B reads done before B swap

        if (st == 0) {
            // prefetch stage-2 B; overlapped with epilogue + next write_A
            for (int i = tid; i < B_CP16; i += NTHREADS)
                CP16(bsa + i * 16, (const char*)g_B2 + i * 16);
            #pragma unroll
            for (int nt = 0; nt < 13; nt++)
                #pragma unroll
                for (int j = 0; j < 4; j++)
                    q[nt][j] = DT2 * acc[nt][j];
            CP_WAIT();                     // stage-2 B resident (bar in next iter)
        } else {
            // output: q5 only for cols 196..205 (h==1, nt 11,12)
            if (h == 1) {
                #pragma unroll
                for (int nt = 11; nt < 13; nt++) {
                    const int NT = 13 + nt;
                    #pragma unroll
                    for (int j = 0; j < 4; j++) {
                        const int col = NT * 8 + 2 * t + (j & 1);
                        if (col >= D1 && col < D2) {
                            const float q5 = DT2 * acc[nt][j];
                            const int row = rowg + r0 + ((j >> 1) << 3);
                            out[(size_t)row * 10 + (col - D1)] = fac * q5;
                        }
                    }
                }
            }
        }
    }
}

extern "C" void kernel_launch(void* const* d_in, const int* in_sizes, int n_in,
                              void* d_out, int out_size)
{
    const float* x    = (const float*)d_in[0];
    const float* fc1w = (const float*)d_in[1];
    const float* fc1b = (const float*)d_in[2];
    const float* fc2w = (const float*)d_in[3];
    const float* fc2b = (const float*)d_in[4];
    const float* fac  = (const float*)d_in[5];
    const float* qn1  = (const float*)d_in[6];
    const float* qn2  = (const float*)d_in[7];
    float* out = (float*)d_out;

    prep_colsum<<<2 * NP, 128>>>(fc1w, qn1, fc2w, qn2);
    const int nfrag = 2 * NKT * NNT * 32;
    prep_frag<<<(nfrag + 255) / 256, 256>>>(fc1w, qn1, fc2w, qn2);

    const int smem = AFRAG_U32 * 4 + B_U32 * 4 + 2 * NP * 4;   // 114816 B
    cudaFuncSetAttribute(net_kernel,
                         cudaFuncAttributeMaxDynamicSharedMemorySize, smem);
    net_kernel<<<BATCH / TM, NTHREADS, smem>>>(x, fc1b, fc2b, fac, out);
}

// round 13
// speedup vs baseline: 1.7325x; 1.0113x over previous
#include <cuda_runtime.h>
#include <cuda_fp16.h>

#define BATCH    65536
#define D1       196
#define D2       206
#define NP       208
#define TM       64          // batch rows per CTA
#define NTHREADS 256
#define DT2      0.01f
#define NKT      13          // k16 tiles
#define NNT      26          // n8 octets
#define KT_U32   1664        // u32 per k16 tile of B (26 nt * 64)
#define B_U32    (NKT * KT_U32)        // 21632 u32 = 86528 B per stage
#define B_CP16   (B_U32 / 4)           // 5408 16-byte packets
#define AFRAG_U32 (4 * NKT * 4 * 32)   // 6656 u32 = 26624 B

typedef unsigned u32;

__device__ float g_diag[2][NP];                     // c2q diagonal + Qn - 1
__device__ __align__(16) u32 g_B1[B_U32];           // fp16 B frags, cg-grouped (stage 1)
__device__ __align__(16) u32 g_B2[B_U32];           // stage 2

// ---------- helpers ----------
__device__ __forceinline__ u32 pack_h2(float lo, float hi) {
    __half2 v = __floats2half2_rn(lo, hi);   // .x = lo (even k)
    return *reinterpret_cast<u32*>(&v);
}
__device__ __forceinline__ void mma16816h(float (&d)[4],
                                          u32 a0, u32 a1, u32 a2, u32 a3,
                                          u32 b0, u32 b1) {
    asm volatile(
        "mma.sync.aligned.m16n8k16.row.col.f32.f16.f16.f32 "
        "{%0,%1,%2,%3}, {%4,%5,%6,%7}, {%8,%9}, {%0,%1,%2,%3};"
        : "+f"(d[0]), "+f"(d[1]), "+f"(d[2]), "+f"(d[3])
        : "r"(a0), "r"(a1), "r"(a2), "r"(a3), "r"(b0), "r"(b1));
}
__device__ __forceinline__ u32 smem_u32(const void* p) {
    u32 a;
    asm("{ .reg .u64 t; cvta.to.shared.u64 t, %1; cvt.u32.u64 %0, t; }" : "=r"(a) : "l"(p));
    return a;
}
#define CP16(dst, src) asm volatile("cp.async.cg.shared.global [%0], [%1], 16;" :: "r"(dst), "l"(src) : "memory")
#define CP_WAIT() asm volatile("cp.async.commit_group;\ncp.async.wait_group 0;" ::: "memory")
#define RGBAR(rg) asm volatile("bar.sync %0, 128;" :: "r"((rg) + 1) : "memory")

// ---------- prep A: column sums -> diagonal values, both stages ----------
__global__ void prep_colsum(const float* __restrict__ C1, const float* __restrict__ Qn1,
                            const float* __restrict__ C2, const float* __restrict__ Qn2)
{
    const int st = blockIdx.x / NP;
    const int j  = blockIdx.x % NP;
    const int n  = st ? D2 : D1;
    const float* C  = st ? C2 : C1;
    const float* Qn = st ? Qn2 : Qn1;
    __shared__ float red[128];
    float s = 0.f;
    if (j < n)
        for (int i = threadIdx.x; i < n; i += 128)
            s += 0.5f * (C[i * n + j] + C[j * n + i]);
    red[threadIdx.x] = s;
    __syncthreads();
    for (int off = 64; off > 0; off >>= 1) {
        if ((int)threadIdx.x < off) red[threadIdx.x] += red[threadIdx.x + off];
        __syncthreads();
    }
    if (threadIdx.x == 0)
        g_diag[st][j] = (j < n) ? (-red[0] + Qn[j * n + j] - 1.0f) : 0.f;
}

// ---------- prep B: build cg-grouped fp16 mma B-fragments from C/Qn ----------
// Column groups over 26 n-tiles: cg0 nt[0,7), cg1 [7,14), cg2 [14,20), cg3 [20,26).
// Within (kt,cg): pairs of n-tiles as uint4-interleaved (3 pairs), 7th tile single.
__global__ void prep_frag(const float* __restrict__ C1, const float* __restrict__ Qn1,
                          const float* __restrict__ C2, const float* __restrict__ Qn2)
{
    const int idx = blockIdx.x * blockDim.x + threadIdx.x;
    if (idx >= 2 * NKT * NNT * 32) return;
    const int lane = idx & 31;
    const int NTg  = (idx >> 5) % NNT;
    const int kt   = ((idx >> 5) / NNT) % NKT;
    const int st   = (idx >> 5) / (NNT * NKT);
    const int nd   = st ? D2 : D1;
    const float* C  = st ? C2 : C1;
    const float* Qn = st ? Qn2 : Qn1;
    const int nn = NTg * 8 + (lane >> 2);
    const int k0 = kt * 16 + (lane & 3) * 2;
    auto elem = [&](int k) -> float {
        if (k >= nd || nn >= nd) return 0.f;
        if (k == nn) return g_diag[st][k];
        return 0.5f * (C[k * nd + nn] + C[nn * nd + k]) + Qn[k * nd + nn];
    };
    const u32 bx = pack_h2(elem(k0),     elem(k0 + 1));
    const u32 by = pack_h2(elem(k0 + 8), elem(k0 + 9));
    const int cg  = (NTg < 7) ? 0 : (NTg < 14) ? 1 : (NTg < 20) ? 2 : 3;
    const int cgs = 7 * cg - (cg == 3 ? 1 : 0);     // 0,7,14,20
    const int ntl = NTg - cgs;
    u32* B = st ? g_B2 : g_B1;
    u32 off;
    if (ntl < 6) off = kt * KT_U32 + cgs * 64 + (ntl >> 1) * 128 + lane * 4 + (ntl & 1) * 2;
    else         off = kt * KT_U32 + cgs * 64 + 384 + lane * 2;
    B[off]     = bx;
    B[off + 1] = by;
}

// ---------- main fused kernel ----------
__global__ void __launch_bounds__(NTHREADS, 2)
net_kernel(const float* __restrict__ x,
           const float* __restrict__ b1,
           const float* __restrict__ b2,
           const float* __restrict__ facp,
           float* __restrict__ out)
{
    extern __shared__ __align__(16) unsigned char smraw[];
    u32*  Afrag = (u32*)smraw;                                  // 26624 B
    u32*  BsU   = (u32*)(smraw + AFRAG_U32 * 4);                // 86528 B
    float* es1  = (float*)(smraw + AFRAG_U32 * 4 + B_U32 * 4);  // 208 f
    float* es2  = es1 + NP;

    const int tid  = threadIdx.x;
    const int lane = tid & 31, warp = tid >> 5;
    const int rg = warp & 1;        // row group (32 rows)
    const int cg = warp >> 1;       // column group
    const int ntcg = 7 - (cg >> 1);                 // 7,7,6,6 n-tiles
    const int cgs  = 7 * cg - (cg == 3 ? 1 : 0);    // 0,7,14,20
    const int g  = lane >> 2, t = lane & 3;
    const int rowg = blockIdx.x * TM;
    const int row0 = rg * 32 + g;   // rows row0 + rt*16 + {0,8}
    const u32 bsa = smem_u32(BsU);

    // start async copy of stage-1 B (never touched before first CP_WAIT)
    for (int i = tid; i < B_CP16; i += NTHREADS)
        CP16(bsa + i * 16, (const char*)g_B1 + i * 16);

    // biases for both stages
    for (int i = tid; i < NP; i += NTHREADS) {
        es1[i] = (i < D1) ? b1[i] : 0.f;
        es2[i] = (i < D2) ? b2[i] : 0.f;
    }

    float q[2][7][4];
    float acc[2][7][4];

    // q0 = x (zero-padded); col pairs never straddle 196 (even boundary)
    #pragma unroll
    for (int rt = 0; rt < 2; rt++) {
        const int row = rowg + row0 + rt * 16;
        #pragma unroll
        for (int ntl = 0; ntl < 7; ntl++) {
            if (ntl >= ntcg) break;
            const int colb = (cgs + ntl) * 8 + 2 * t;
            if (colb < D1) {
                const float2 v0 = *(const float2*)&x[(size_t)row * D1 + colb];
                const float2 v1 = *(const float2*)&x[(size_t)(row + 8) * D1 + colb];
                q[rt][ntl][0] = v0.x; q[rt][ntl][1] = v0.y;
                q[rt][ntl][2] = v1.x; q[rt][ntl][3] = v1.y;
            } else {
                q[rt][ntl][0] = q[rt][ntl][1] = q[rt][ntl][2] = q[rt][ntl][3] = 0.f;
            }
        }
    }
    __syncthreads();   // es1/es2 writes visible before first acc init

    // write A = 4*sin(1.1 q) as single-fp16 fragments (STS.64 per (rt,ntl))
    auto write_A = [&] {
        #pragma unroll
        for (int rt = 0; rt < 2; rt++) {
            #pragma unroll
            for (int ntl = 0; ntl < 7; ntl++) {
                if (ntl >= ntcg) break;
                const int NTg = cgs + ntl;
                const int kt = NTg >> 1;
                const int rb = (NTg & 1) << 1;
                uint2 w;
                w.x = pack_h2(4.f * __sinf(1.1f * q[rt][ntl][0]),
                              4.f * __sinf(1.1f * q[rt][ntl][1]));
                w.y = pack_h2(4.f * __sinf(1.1f * q[rt][ntl][2]),
                              4.f * __sinf(1.1f * q[rt][ntl][3]));
                *(uint2*)&Afrag[(((rg * 2 + rt) * 13 + kt) * 32 + lane) * 4 + rb] = w;
            }
        }
    };

    // acc += A @ M; each B fragment (LDS) feeds MMAs of BOTH row-tiles (2x reuse)
    const uint4* A0p = (const uint4*)Afrag + (rg * 2 * 13) * 32 + lane;
    const uint4* A1p = A0p + 13 * 32;
    const u32*   Bb  = BsU + cgs * 64;

    auto gemm_full = [&] {
        #pragma unroll 1
        for (int kt = 0; kt < NKT; kt++) {
            const uint4 a0 = A0p[kt * 32];
            const uint4 a1 = A1p[kt * 32];
            const u32* Bk = Bb + kt * KT_U32;
            #pragma unroll
            for (int p = 0; p < 3; p++) {
                const uint4 b = *(const uint4*)(Bk + p * 128 + lane * 4);
                mma16816h(acc[0][2 * p],     a0.x, a0.y, a0.z, a0.w, b.x, b.y);
                mma16816h(acc[1][2 * p],     a1.x, a1.y, a1.z, a1.w, b.x, b.y);
                mma16816h(acc[0][2 * p + 1], a0.x, a0.y, a0.z, a0.w, b.z, b.w);
                mma16816h(acc[1][2 * p + 1], a1.x, a1.y, a1.z, a1.w, b.z, b.w);
            }
            if (ntcg == 7) {
                const uint2 b2 = *(const uint2*)(Bk + 384 + lane * 2);
                mma16816h(acc[0][6], a0.x, a0.y, a0.z, a0.w, b2.x, b2.y);
                mma16816h(acc[1][6], a1.x, a1.y, a1.z, a1.w, b2.x, b2.y);
            }
        }
    };
    // skinny: cols 192..207 -> cg3 warps, local tiles 4,5 (pair p=2)
    auto gemm_skinny = [&] {
        if (cg == 3) {
            #pragma unroll 1
            for (int kt = 0; kt < NKT; kt++) {
                const uint4 a0 = A0p[kt * 32];
                const uint4 a1 = A1p[kt * 32];
                const u32* Bk = Bb + kt * KT_U32;
                const uint4 b = *(const uint4*)(Bk + 2 * 128 + lane * 4);
                mma16816h(acc[0][4], a0.x, a0.y, a0.z, a0.w, b.x, b.y);
                mma16816h(acc[1][4], a1.x, a1.y, a1.z, a1.w, b.x, b.y);
                mma16816h(acc[0][5], a0.x, a0.y, a0.z, a0.w, b.z, b.w);
                mma16816h(acc[1][5], a1.x, a1.y, a1.z, a1.w, b.z, b.w);
            }
        }
    };

    const float fac = *facp;

    #pragma unroll 1
    for (int st = 0; st < 2; st++) {
        const float* es = st ? es2 : es1;

        // ---- gemm 1: acc = 4e; A = 4*s(q0)  =>  acc = 4*(e + s0@M) = 4*a0 ----
        #pragma unroll
        for (int ntl = 0; ntl < 7; ntl++) {
            if (ntl >= ntcg) break;
            const float2 e2 = *(const float2*)&es[(cgs + ntl) * 8 + 2 * t];
            #pragma unroll
            for (int rt = 0; rt < 2; rt++) {
                acc[rt][ntl][0] = 4.f * e2.x; acc[rt][ntl][1] = 4.f * e2.y;
                acc[rt][ntl][2] = 4.f * e2.x; acc[rt][ntl][3] = 4.f * e2.y;
            }
        }
        write_A();
        if (st == 0) CP_WAIT();            // this stage's B resident (own copies)
        __syncthreads();                   // all threads' B copies + A visible
        gemm_full();
        RGBAR(rg);                         // A-frag reads done within row group

        // ---- readback: q2,q3; A = u = 2*s(q2)+s(q3);
        //      acc_old = 4e + 4*s0@M; fold: acc = q3/dt^2 + 3e + acc_old ----
        #pragma unroll
        for (int ntl = 0; ntl < 7; ntl++) {
            if (ntl >= ntcg) break;
            const int NTg = cgs + ntl;
            const int kt = NTg >> 1;
            const int rb = (NTg & 1) << 1;
            const float2 e2 = *(const float2*)&es[NTg * 8 + 2 * t];
            #pragma unroll
            for (int rt = 0; rt < 2; rt++) {
                float u[4];
                #pragma unroll
                for (int j = 0; j < 4; j++) {
                    const float ej = (j & 1) ? e2.y : e2.x;
                    const float a0v = 0.25f * acc[rt][ntl][j];
                    const float q2 = q[rt][ntl][j] + DT2 * a0v;
                    const float q3 = q[rt][ntl][j] + 3.0f * DT2 * a0v;
                    u[j] = 2.0f * __sinf(1.1f * q2) + __sinf(1.1f * q3);
                    acc[rt][ntl][j] = q3 * (1.0f / DT2) + 3.0f * ej + acc[rt][ntl][j];
                }
                uint2 w;
                w.x = pack_h2(u[0], u[1]);
                w.y = pack_h2(u[2], u[3]);
                *(uint2*)&Afrag[(((rg * 2 + rt) * 13 + kt) * 32 + lane) * 4 + rb] = w;
            }
        }
        RGBAR(rg);                         // new A visible within row group

        // ---- gemm 2: acc += u @ M ;  q5 = dt^2 * acc ----
        if (st == 0) gemm_full();
        else         gemm_skinny();
        __syncthreads();                   // all B reads done before B swap

        if (st == 0) {
            // prefetch stage-2 B; overlapped with epilogue + next write_A
            for (int i = tid; i < B_CP16; i += NTHREADS)
                CP16(bsa + i * 16, (const char*)g_B2 + i * 16);
            #pragma unroll
            for (int rt = 0; rt < 2; rt++)
                #pragma unroll
                for (int ntl = 0; ntl < 7; ntl++) {
                    if (ntl >= ntcg) break;
                    #pragma unroll
                    for (int j = 0; j < 4; j++)
                        q[rt][ntl][j] = DT2 * acc[rt][ntl][j];
                }
            CP_WAIT();                     // own copies done (full bar next iter)
        } else {
            // output: q5 only for cols 196..205 (cg3, local tiles 4,5)
            if (cg == 3) {
                #pragma unroll
                for (int ntl = 4; ntl < 6; ntl++) {
                    #pragma unroll
                    for (int rt = 0; rt < 2; rt++) {
                        #pragma unroll
                        for (int j = 0; j < 4; j++) {
                            const int col = (cgs + ntl) * 8 + 2 * t + (j & 1);
                            if (col >= D1 && col < D2) {
                                const float q5 = DT2 * acc[rt][ntl][j];
                                const int row = rowg + row0 + rt * 16 + ((j >> 1) << 3);
                                out[(size_t)row * 10 + (col - D1)] = fac * q5;
                            }
                        }
                    }
                }
            }
        }
    }
}

extern "C" void kernel_launch(void* const* d_in, const int* in_sizes, int n_in,
                              void* d_out, int out_size)
{
    const float* x    = (const float*)d_in[0];
    const float* fc1w = (const float*)d_in[1];
    const float* fc1b = (const float*)d_in[2];
    const float* fc2w = (const float*)d_in[3];
    const float* fc2b = (const float*)d_in[4];
    const float* fac  = (const float*)d_in[5];
    const float* qn1  = (const float*)d_in[6];
    const float* qn2  = (const float*)d_in[7];
    float* out = (float*)d_out;

    prep_colsum<<<2 * NP, 128>>>(fc1w, qn1, fc2w, qn2);
    const int nfrag = 2 * NKT * NNT * 32;
    prep_frag<<<(nfrag + 255) / 256, 256>>>(fc1w, qn1, fc2w, qn2);

    const int smem = AFRAG_U32 * 4 + B_U32 * 4 + 2 * NP * 4;   // 114816 B
    cudaFuncSetAttribute(net_kernel,
                         cudaFuncAttributeMaxDynamicSharedMemorySize, smem);
    net_kernel<<<BATCH / TM, NTHREADS, smem>>>(x, fc1b, fc2b, fac, out);
}